// round 2
// baseline (speedup 1.0000x reference)
#include <cuda_runtime.h>
#include <math.h>

#define N_NODES   100000
#define N_EDGES   1600000
#define N_FEAT    50
#define HIDDEN    16
#define N_CLASSES 10

// ---- scratch (static device globals; no allocation in kernel_launch) ----
__device__ int   g_deg[N_NODES];
__device__ float g_dinv[N_NODES];
__device__ int   g_rowptr[N_NODES + 1];
__device__ int   g_woff[N_NODES];
__device__ int   g_csr[N_EDGES];
__device__ __align__(16) float g_xw0[N_NODES * HIDDEN];  // x @ w1_0 + b1
__device__ __align__(16) float g_xp1[N_NODES * HIDDEN];  // x @ w1_1
__device__ __align__(16) float g_h  [N_NODES * HIDDEN];  // relu layer-1 output
__device__ __align__(16) float g_hw [N_NODES * HIDDEN];  // h @ w2_0 + b2 (padded 10->16)
__device__ __align__(16) float g_hp [N_NODES * HIDDEN];  // h @ w2_1      (padded 10->16)

// ---- K0: zero degree counts (re-run every replay) ----
__global__ void k_zero() {
    int i = blockIdx.x * blockDim.x + threadIdx.x;
    if (i < N_NODES) g_deg[i] = 0;
}

// ---- K1: in-degree count ----
__global__ void k_count(const int* __restrict__ ei) {
    int e = blockIdx.x * blockDim.x + threadIdx.x;
    if (e < N_EDGES) {
        int d = ei[N_EDGES + e];   // dst row
        atomicAdd(&g_deg[d], 1);
    }
}

// ---- K2: single-block exclusive scan -> rowptr/woff, plus dinv ----
__global__ void k_scan() {
    const int CH = (N_NODES + 1023) / 1024;  // 98
    int t = threadIdx.x;
    int base = t * CH;
    int s = 0;
    for (int j = 0; j < CH; j++) {
        int i = base + j;
        if (i < N_NODES) s += g_deg[i];
    }
    __shared__ int sh[1024];
    sh[t] = s;
    __syncthreads();
    for (int off = 1; off < 1024; off <<= 1) {
        int v = (t >= off) ? sh[t - off] : 0;
        __syncthreads();
        sh[t] += v;
        __syncthreads();
    }
    int run = (t > 0) ? sh[t - 1] : 0;
    for (int j = 0; j < CH; j++) {
        int i = base + j;
        if (i < N_NODES) {
            int d = g_deg[i];
            g_rowptr[i] = run;
            g_woff[i]   = run;
            g_dinv[i]   = (d > 0) ? rsqrtf((float)d) : 0.0f;
            run += d;
        }
    }
    if (t == 1023) g_rowptr[N_NODES] = sh[1023];
}

// ---- K3: scatter edges into CSR (payload = src id) ----
__global__ void k_scatter(const int* __restrict__ ei) {
    int e = blockIdx.x * blockDim.x + threadIdx.x;
    if (e < N_EDGES) {
        int s = ei[e];              // src row
        int d = ei[N_EDGES + e];    // dst row
        int pos = atomicAdd(&g_woff[d], 1);
        g_csr[pos] = s;
    }
}

// ---- K4: layer-1 projections: xw0 = x@w1_0 + b1, xp1 = x@w1_1 ----
__global__ void k_proj1(const float* __restrict__ x,
                        const float* __restrict__ w0,
                        const float* __restrict__ w1,
                        const float* __restrict__ b1) {
    __shared__ float sw0[N_FEAT * HIDDEN];
    __shared__ float sw1[N_FEAT * HIDDEN];
    __shared__ float sb[HIDDEN];
    for (int i = threadIdx.x; i < N_FEAT * HIDDEN; i += blockDim.x) {
        sw0[i] = w0[i];
        sw1[i] = w1[i];
    }
    if (threadIdx.x < HIDDEN) sb[threadIdx.x] = b1[threadIdx.x];
    __syncthreads();

    int n = blockIdx.x * blockDim.x + threadIdx.x;
    if (n >= N_NODES) return;

    float a0[HIDDEN];
    float a1[HIDDEN];
#pragma unroll
    for (int c = 0; c < HIDDEN; c++) { a0[c] = 0.0f; a1[c] = 0.0f; }

    const float* xr = x + (size_t)n * N_FEAT;
#pragma unroll 10
    for (int k = 0; k < N_FEAT; k++) {
        float xv = xr[k];
#pragma unroll
        for (int c = 0; c < HIDDEN; c++) {
            a0[c] = fmaf(xv, sw0[k * HIDDEN + c], a0[c]);
            a1[c] = fmaf(xv, sw1[k * HIDDEN + c], a1[c]);
        }
    }
    float4* o0 = (float4*)(g_xw0 + (size_t)n * HIDDEN);
    float4* o1 = (float4*)(g_xp1 + (size_t)n * HIDDEN);
#pragma unroll
    for (int q = 0; q < 4; q++) {
        float4 v0, v1;
        v0.x = a0[q * 4 + 0] + sb[q * 4 + 0];
        v0.y = a0[q * 4 + 1] + sb[q * 4 + 1];
        v0.z = a0[q * 4 + 2] + sb[q * 4 + 2];
        v0.w = a0[q * 4 + 3] + sb[q * 4 + 3];
        v1.x = a1[q * 4 + 0];
        v1.y = a1[q * 4 + 1];
        v1.z = a1[q * 4 + 2];
        v1.w = a1[q * 4 + 3];
        o0[q] = v0;
        o1[q] = v1;
    }
}

// ---- K5: layer-1 aggregation + bias/relu. 16 lanes per node. ----
__global__ void k_agg1() {
    int gid  = blockIdx.x * blockDim.x + threadIdx.x;   // exactly N_NODES*16
    int node = gid >> 4;
    int c    = gid & 15;
    int b = g_rowptr[node];
    int e = g_rowptr[node + 1];
    float acc = 0.0f;
    for (int j = b; j < e; j++) {
        int s = __ldg(&g_csr[j]);
        acc = fmaf(__ldg(&g_dinv[s]), __ldg(&g_xp1[s * HIDDEN + c]), acc);
    }
    float v = g_xw0[node * HIDDEN + c] + g_dinv[node] * acc;
    g_h[node * HIDDEN + c] = fmaxf(v, 0.0f);
}

// ---- K6: layer-2 projections (padded to stride 16, pad = 0) ----
__global__ void k_proj2(const float* __restrict__ w0,
                        const float* __restrict__ w1,
                        const float* __restrict__ b2) {
    __shared__ float sw0[HIDDEN * N_CLASSES];
    __shared__ float sw1[HIDDEN * N_CLASSES];
    __shared__ float sb[N_CLASSES];
    for (int i = threadIdx.x; i < HIDDEN * N_CLASSES; i += blockDim.x) {
        sw0[i] = w0[i];
        sw1[i] = w1[i];
    }
    if (threadIdx.x < N_CLASSES) sb[threadIdx.x] = b2[threadIdx.x];
    __syncthreads();

    int n = blockIdx.x * blockDim.x + threadIdx.x;
    if (n >= N_NODES) return;

    float hr[HIDDEN];
    const float4* hin = (const float4*)(g_h + (size_t)n * HIDDEN);
#pragma unroll
    for (int q = 0; q < 4; q++) {
        float4 v = hin[q];
        hr[q * 4 + 0] = v.x; hr[q * 4 + 1] = v.y;
        hr[q * 4 + 2] = v.z; hr[q * 4 + 3] = v.w;
    }
    float a0[HIDDEN];
    float a1[HIDDEN];
#pragma unroll
    for (int c = 0; c < HIDDEN; c++) { a0[c] = 0.0f; a1[c] = 0.0f; }
#pragma unroll
    for (int k = 0; k < HIDDEN; k++) {
#pragma unroll
        for (int c = 0; c < N_CLASSES; c++) {
            a0[c] = fmaf(hr[k], sw0[k * N_CLASSES + c], a0[c]);
            a1[c] = fmaf(hr[k], sw1[k * N_CLASSES + c], a1[c]);
        }
    }
#pragma unroll
    for (int c = 0; c < N_CLASSES; c++) a0[c] += sb[c];

    float4* o0 = (float4*)(g_hw + (size_t)n * HIDDEN);
    float4* o1 = (float4*)(g_hp + (size_t)n * HIDDEN);
#pragma unroll
    for (int q = 0; q < 4; q++) {
        float4 v0, v1;
        v0.x = a0[q * 4 + 0]; v0.y = a0[q * 4 + 1];
        v0.z = a0[q * 4 + 2]; v0.w = a0[q * 4 + 3];
        v1.x = a1[q * 4 + 0]; v1.y = a1[q * 4 + 1];
        v1.z = a1[q * 4 + 2]; v1.w = a1[q * 4 + 3];
        o0[q] = v0;
        o1[q] = v1;
    }
}

// ---- K7: layer-2 aggregation + log_softmax. 16 lanes per node. ----
__global__ void k_agg2(float* __restrict__ out) {
    int gid  = blockIdx.x * blockDim.x + threadIdx.x;   // exactly N_NODES*16
    int node = gid >> 4;
    int c    = gid & 15;
    int b = g_rowptr[node];
    int e = g_rowptr[node + 1];
    float acc = 0.0f;
    for (int j = b; j < e; j++) {
        int s = __ldg(&g_csr[j]);
        acc = fmaf(__ldg(&g_dinv[s]), __ldg(&g_hp[s * HIDDEN + c]), acc);
    }
    float logit = g_hw[node * HIDDEN + c] + g_dinv[node] * acc;
    bool valid = (c < N_CLASSES);
    float lv = valid ? logit : -1e30f;
    float m = lv;
#pragma unroll
    for (int o = 8; o > 0; o >>= 1)
        m = fmaxf(m, __shfl_xor_sync(0xffffffffu, m, o, 16));
    float ex = valid ? expf(logit - m) : 0.0f;
    float ssum = ex;
#pragma unroll
    for (int o = 8; o > 0; o >>= 1)
        ssum += __shfl_xor_sync(0xffffffffu, ssum, o, 16);
    if (valid)
        out[(size_t)node * N_CLASSES + c] = logit - m - logf(ssum);
}

extern "C" void kernel_launch(void* const* d_in, const int* in_sizes, int n_in,
                              void* d_out, int out_size) {
    const float* x    = (const float*)d_in[0];
    const int*   ei   = (const int*)d_in[1];     // int32: JAX x64 disabled
    const float* w1_0 = (const float*)d_in[2];
    const float* w1_1 = (const float*)d_in[3];
    const float* b1   = (const float*)d_in[4];
    const float* w2_0 = (const float*)d_in[5];
    const float* w2_1 = (const float*)d_in[6];
    const float* b2   = (const float*)d_in[7];
    float* out = (float*)d_out;

    const int EB = 256;
    k_zero   <<<(N_NODES + 255) / 256, 256>>>();
    k_count  <<<(N_EDGES + EB - 1) / EB, EB>>>(ei);
    k_scan   <<<1, 1024>>>();
    k_scatter<<<(N_EDGES + EB - 1) / EB, EB>>>(ei);
    k_proj1  <<<(N_NODES + 255) / 256, 256>>>(x, w1_0, w1_1, b1);
    k_agg1   <<<(N_NODES * HIDDEN) / 256, 256>>>();
    k_proj2  <<<(N_NODES + 255) / 256, 256>>>(w2_0, w2_1, b2);
    k_agg2   <<<(N_NODES * HIDDEN) / 256, 256>>>(out);
}

// round 3
// speedup vs baseline: 3.0085x; 3.0085x over previous
#include <cuda_runtime.h>
#include <math.h>

#define N_NODES   100000
#define N_EDGES   1600000
#define N_FEAT    50
#define HIDDEN    16
#define N_CLASSES 10
#define NB_SCAN   392          // ceil(100000/256)

// ---- scratch (static device globals; no allocation in kernel_launch) ----
__device__ int   g_deg[N_NODES];
__device__ float g_dinv[N_NODES];
__device__ int   g_rowptr[N_NODES + 1];
__device__ int   g_woff[N_NODES];
__device__ int   g_csr[N_EDGES];
__device__ int   g_bpre[NB_SCAN];
__device__ int   g_bsum[NB_SCAN];
__device__ __align__(16) float g_xw0[N_NODES * HIDDEN];  // x @ w1_0 + b1
__device__ __align__(16) float g_xp1[N_NODES * HIDDEN];  // dinv[n] * (x @ w1_1)
__device__ __align__(16) float g_hw [N_NODES * HIDDEN];  // h @ w2_0 + b2 (pad 10->16)
__device__ __align__(16) float g_hp [N_NODES * HIDDEN];  // dinv[n] * (h @ w2_1)

// ---- K0: zero degree counts (re-run every replay) ----
__global__ void k_zero() {
    int i = blockIdx.x * blockDim.x + threadIdx.x;
    if (i < N_NODES) g_deg[i] = 0;
}

// ---- K1: in-degree count, 4 edges per thread ----
__global__ void k_count(const int* __restrict__ ei) {
    int e4 = blockIdx.x * blockDim.x + threadIdx.x;   // N_EDGES/4 threads
    if (e4 < N_EDGES / 4) {
        int4 d = ((const int4*)(ei + N_EDGES))[e4];
        atomicAdd(&g_deg[d.x], 1);
        atomicAdd(&g_deg[d.y], 1);
        atomicAdd(&g_deg[d.z], 1);
        atomicAdd(&g_deg[d.w], 1);
    }
}

// ---- K2a: per-block reduction of deg ----
__global__ void k_red() {
    __shared__ int sh[256];
    int t = threadIdx.x;
    int i = blockIdx.x * 256 + t;
    sh[t] = (i < N_NODES) ? g_deg[i] : 0;
    __syncthreads();
#pragma unroll
    for (int o = 128; o > 0; o >>= 1) {
        if (t < o) sh[t] += sh[t + o];
        __syncthreads();
    }
    if (t == 0) g_bsum[blockIdx.x] = sh[0];
}

// ---- K2b: single-block exclusive scan of 392 block sums ----
__global__ void k_scanb() {
    __shared__ int sh[512];
    int t = threadIdx.x;
    int v = (t < NB_SCAN) ? g_bsum[t] : 0;
    sh[t] = v;
    __syncthreads();
    for (int o = 1; o < 512; o <<= 1) {
        int u = (t >= o) ? sh[t - o] : 0;
        __syncthreads();
        sh[t] += u;
        __syncthreads();
    }
    if (t < NB_SCAN) g_bpre[t] = sh[t] - v;   // exclusive prefix
    if (t == NB_SCAN - 1) g_rowptr[N_NODES] = sh[t];
}

// ---- K2c: per-block re-scan -> rowptr/woff/dinv ----
__global__ void k_scanc() {
    __shared__ int sh[256];
    int t = threadIdx.x;
    int i = blockIdx.x * 256 + t;
    int d = (i < N_NODES) ? g_deg[i] : 0;
    sh[t] = d;
    __syncthreads();
    for (int o = 1; o < 256; o <<= 1) {
        int u = (t >= o) ? sh[t - o] : 0;
        __syncthreads();
        sh[t] += u;
        __syncthreads();
    }
    if (i < N_NODES) {
        int run = g_bpre[blockIdx.x] + sh[t] - d;
        g_rowptr[i] = run;
        g_woff[i]   = run;
        g_dinv[i]   = (d > 0) ? rsqrtf((float)d) : 0.0f;
    }
}

// ---- K3: scatter edges into CSR (payload = src id), 4 edges/thread ----
__global__ void k_scatter(const int* __restrict__ ei) {
    int e4 = blockIdx.x * blockDim.x + threadIdx.x;
    if (e4 < N_EDGES / 4) {
        int4 s = ((const int4*)ei)[e4];
        int4 d = ((const int4*)(ei + N_EDGES))[e4];
        int p;
        p = atomicAdd(&g_woff[d.x], 1); g_csr[p] = s.x;
        p = atomicAdd(&g_woff[d.y], 1); g_csr[p] = s.y;
        p = atomicAdd(&g_woff[d.z], 1); g_csr[p] = s.z;
        p = atomicAdd(&g_woff[d.w], 1); g_csr[p] = s.w;
    }
}

// ---- K4: layer-1 projections: xw0 = x@w1_0 + b1, xp1 = dinv*(x@w1_1) ----
__global__ void k_proj1(const float* __restrict__ x,
                        const float* __restrict__ w0,
                        const float* __restrict__ w1,
                        const float* __restrict__ b1) {
    __shared__ float sw0[N_FEAT * HIDDEN];
    __shared__ float sw1[N_FEAT * HIDDEN];
    __shared__ float sb[HIDDEN];
    for (int i = threadIdx.x; i < N_FEAT * HIDDEN; i += blockDim.x) {
        sw0[i] = w0[i];
        sw1[i] = w1[i];
    }
    if (threadIdx.x < HIDDEN) sb[threadIdx.x] = b1[threadIdx.x];
    __syncthreads();

    int n = blockIdx.x * blockDim.x + threadIdx.x;
    if (n >= N_NODES) return;

    float a0[HIDDEN];
    float a1[HIDDEN];
#pragma unroll
    for (int c = 0; c < HIDDEN; c++) { a0[c] = 0.0f; a1[c] = 0.0f; }

    const float* xr = x + (size_t)n * N_FEAT;
#pragma unroll 10
    for (int k = 0; k < N_FEAT; k++) {
        float xv = xr[k];
#pragma unroll
        for (int c = 0; c < HIDDEN; c++) {
            a0[c] = fmaf(xv, sw0[k * HIDDEN + c], a0[c]);
            a1[c] = fmaf(xv, sw1[k * HIDDEN + c], a1[c]);
        }
    }
    float dn = g_dinv[n];
    float4* o0 = (float4*)(g_xw0 + (size_t)n * HIDDEN);
    float4* o1 = (float4*)(g_xp1 + (size_t)n * HIDDEN);
#pragma unroll
    for (int q = 0; q < 4; q++) {
        float4 v0, v1;
        v0.x = a0[q * 4 + 0] + sb[q * 4 + 0];
        v0.y = a0[q * 4 + 1] + sb[q * 4 + 1];
        v0.z = a0[q * 4 + 2] + sb[q * 4 + 2];
        v0.w = a0[q * 4 + 3] + sb[q * 4 + 3];
        v1.x = dn * a1[q * 4 + 0];
        v1.y = dn * a1[q * 4 + 1];
        v1.z = dn * a1[q * 4 + 2];
        v1.w = dn * a1[q * 4 + 3];
        o0[q] = v0;
        o1[q] = v1;
    }
}

// ---- K5: fused layer-1 aggregation + relu + layer-2 projections ----
// 16 lanes per node. h kept in registers; shuffle matmul for layer 2.
__global__ void k_agg1p2(const float* __restrict__ w0,
                         const float* __restrict__ w1,
                         const float* __restrict__ b2) {
    __shared__ float sw0[HIDDEN * HIDDEN];   // padded 16x16, cols 10..15 = 0
    __shared__ float sw1[HIDDEN * HIDDEN];
    __shared__ float sb[HIDDEN];
    int t = threadIdx.x;
    {
        int k = t >> 4, c = t & 15;          // blockDim = 256 covers all 16x16
        sw0[t] = (c < N_CLASSES) ? w0[k * N_CLASSES + c] : 0.0f;
        sw1[t] = (c < N_CLASSES) ? w1[k * N_CLASSES + c] : 0.0f;
    }
    if (t < HIDDEN) sb[t] = (t < N_CLASSES) ? b2[t] : 0.0f;
    __syncthreads();

    int gid  = blockIdx.x * blockDim.x + t;  // exactly N_NODES*16
    int node = gid >> 4;
    int c    = gid & 15;
    int b = g_rowptr[node];
    int e = g_rowptr[node + 1];
    float acc = 0.0f;
#pragma unroll 4
    for (int j = b; j < e; j++) {
        int s = __ldg(&g_csr[j]);
        acc += __ldg(&g_xp1[s * HIDDEN + c]);
    }
    float dn = g_dinv[node];
    float h  = fmaxf(g_xw0[node * HIDDEN + c] + dn * acc, 0.0f);

    // layer-2 projection via 16-lane shuffle matmul
    float a0 = sb[c];
    float a1 = 0.0f;
#pragma unroll
    for (int k = 0; k < HIDDEN; k++) {
        float hk = __shfl_sync(0xffffffffu, h, k, 16);
        a0 = fmaf(hk, sw0[k * HIDDEN + c], a0);
        a1 = fmaf(hk, sw1[k * HIDDEN + c], a1);
    }
    g_hw[node * HIDDEN + c] = a0;
    g_hp[node * HIDDEN + c] = dn * a1;
}

// ---- K6: layer-2 aggregation + log_softmax. 16 lanes per node. ----
__global__ void k_agg2(float* __restrict__ out) {
    int gid  = blockIdx.x * blockDim.x + threadIdx.x;   // exactly N_NODES*16
    int node = gid >> 4;
    int c    = gid & 15;
    int b = g_rowptr[node];
    int e = g_rowptr[node + 1];
    float acc = 0.0f;
#pragma unroll 4
    for (int j = b; j < e; j++) {
        int s = __ldg(&g_csr[j]);
        acc += __ldg(&g_hp[s * HIDDEN + c]);
    }
    float logit = g_hw[node * HIDDEN + c] + g_dinv[node] * acc;
    bool valid = (c < N_CLASSES);
    float lv = valid ? logit : -1e30f;
    float m = lv;
#pragma unroll
    for (int o = 8; o > 0; o >>= 1)
        m = fmaxf(m, __shfl_xor_sync(0xffffffffu, m, o, 16));
    float ex = valid ? expf(logit - m) : 0.0f;
    float ssum = ex;
#pragma unroll
    for (int o = 8; o > 0; o >>= 1)
        ssum += __shfl_xor_sync(0xffffffffu, ssum, o, 16);
    if (valid)
        out[(size_t)node * N_CLASSES + c] = logit - m - logf(ssum);
}

extern "C" void kernel_launch(void* const* d_in, const int* in_sizes, int n_in,
                              void* d_out, int out_size) {
    const float* x    = (const float*)d_in[0];
    const int*   ei   = (const int*)d_in[1];     // int32: JAX x64 disabled
    const float* w1_0 = (const float*)d_in[2];
    const float* w1_1 = (const float*)d_in[3];
    const float* b1   = (const float*)d_in[4];
    const float* w2_0 = (const float*)d_in[5];
    const float* w2_1 = (const float*)d_in[6];
    const float* b2   = (const float*)d_in[7];
    float* out = (float*)d_out;

    const int E4 = N_EDGES / 4;
    k_zero   <<<NB_SCAN, 256>>>();
    k_count  <<<(E4 + 255) / 256, 256>>>(ei);
    k_red    <<<NB_SCAN, 256>>>();
    k_scanb  <<<1, 512>>>();
    k_scanc  <<<NB_SCAN, 256>>>();
    k_scatter<<<(E4 + 255) / 256, 256>>>(ei);
    k_proj1  <<<(N_NODES + 255) / 256, 256>>>(x, w1_0, w1_1, b1);
    k_agg1p2 <<<(N_NODES * HIDDEN) / 256, 256>>>(w2_0, w2_1, b2);
    k_agg2   <<<(N_NODES * HIDDEN) / 256, 256>>>(out);
}

// round 4
// speedup vs baseline: 3.4589x; 1.1497x over previous
#include <cuda_runtime.h>
#include <math.h>

#define N_NODES   100000
#define N_EDGES   1600000
#define N_FEAT    50
#define HIDDEN    16
#define N_CLASSES 10
#define NB_SCAN   392          // ceil(100000/256)

// ---- scratch (static device globals; zero-initialized at load) ----
__device__ int   g_deg[N_NODES];
__device__ float g_dinv[N_NODES];
__device__ int   g_rowptr[N_NODES + 1];
__device__ int   g_woff[N_NODES];
__device__ int   g_csr[N_EDGES];
__device__ int   g_bpre[NB_SCAN];
__device__ int   g_bsum[NB_SCAN];
__device__ __align__(16) float g_xw0[N_NODES * HIDDEN];  // x@w1_0 + b1
__device__ __align__(16) float g_xp1[N_NODES * HIDDEN];  // dinv*(x@w1_1)
__device__ __align__(16) float g_hw [N_NODES * HIDDEN];  // h@w2_0 + b2 (pad 10->16)
__device__ __align__(16) float g_hp [N_NODES * HIDDEN];  // dinv*(h@w2_1)

// ---- K1: in-degree count, 8 edges per thread ----
__global__ void k_count(const int* __restrict__ ei) {
    int e8 = blockIdx.x * blockDim.x + threadIdx.x;
    if (e8 < N_EDGES / 8) {
        const int4* dp = (const int4*)(ei + N_EDGES);
        int4 d0 = dp[e8 * 2];
        int4 d1 = dp[e8 * 2 + 1];
        atomicAdd(&g_deg[d0.x], 1); atomicAdd(&g_deg[d0.y], 1);
        atomicAdd(&g_deg[d0.z], 1); atomicAdd(&g_deg[d0.w], 1);
        atomicAdd(&g_deg[d1.x], 1); atomicAdd(&g_deg[d1.y], 1);
        atomicAdd(&g_deg[d1.z], 1); atomicAdd(&g_deg[d1.w], 1);
    }
}

// ---- K2a: per-block reduction of deg ----
__global__ void k_red() {
    __shared__ int sh[256];
    int t = threadIdx.x;
    int i = blockIdx.x * 256 + t;
    sh[t] = (i < N_NODES) ? g_deg[i] : 0;
    __syncthreads();
#pragma unroll
    for (int o = 128; o > 0; o >>= 1) {
        if (t < o) sh[t] += sh[t + o];
        __syncthreads();
    }
    if (t == 0) g_bsum[blockIdx.x] = sh[0];
}

// ---- K2b: single-block shuffle scan of 392 block sums ----
__global__ void k_scanb() {
    int t = threadIdx.x;
    int v = (t < NB_SCAN) ? g_bsum[t] : 0;
    int lane = t & 31, w = t >> 5;
    int inc = v;
#pragma unroll
    for (int o = 1; o < 32; o <<= 1) {
        int u = __shfl_up_sync(0xffffffffu, inc, o);
        if (lane >= o) inc += u;
    }
    __shared__ int ws[16];
    if (lane == 31) ws[w] = inc;
    __syncthreads();
    if (w == 0) {
        int s = (lane < 16) ? ws[lane] : 0;
#pragma unroll
        for (int o = 1; o < 16; o <<= 1) {
            int u = __shfl_up_sync(0xffffffffu, s, o);
            if (lane >= o) s += u;
        }
        if (lane < 16) ws[lane] = s;
    }
    __syncthreads();
    int incl = ((w > 0) ? ws[w - 1] : 0) + inc;
    if (t < NB_SCAN) g_bpre[t] = incl - v;            // exclusive prefix
    if (t == NB_SCAN - 1) g_rowptr[N_NODES] = incl;   // total
}

// ---- K2c: per-block re-scan -> rowptr/woff/dinv; resets deg for next replay ----
__global__ void k_scanc() {
    __shared__ int sh[256];
    int t = threadIdx.x;
    int i = blockIdx.x * 256 + t;
    int d = (i < N_NODES) ? g_deg[i] : 0;
    sh[t] = d;
    __syncthreads();
    for (int o = 1; o < 256; o <<= 1) {
        int u = (t >= o) ? sh[t - o] : 0;
        __syncthreads();
        sh[t] += u;
        __syncthreads();
    }
    if (i < N_NODES) {
        int run = g_bpre[blockIdx.x] + sh[t] - d;
        g_rowptr[i] = run;
        g_woff[i]   = run;
        g_dinv[i]   = (d > 0) ? rsqrtf((float)d) : 0.0f;
        g_deg[i]    = 0;     // ready for next replay
    }
}

// ---- K3: scatter edges into CSR (payload = src id), 8 edges/thread ----
__global__ void k_scatter(const int* __restrict__ ei) {
    int e8 = blockIdx.x * blockDim.x + threadIdx.x;
    if (e8 < N_EDGES / 8) {
        const int4* sp = (const int4*)ei;
        const int4* dp = (const int4*)(ei + N_EDGES);
        int4 s0 = sp[e8 * 2], s1 = sp[e8 * 2 + 1];
        int4 d0 = dp[e8 * 2], d1 = dp[e8 * 2 + 1];
        int p;
        p = atomicAdd(&g_woff[d0.x], 1); g_csr[p] = s0.x;
        p = atomicAdd(&g_woff[d0.y], 1); g_csr[p] = s0.y;
        p = atomicAdd(&g_woff[d0.z], 1); g_csr[p] = s0.z;
        p = atomicAdd(&g_woff[d0.w], 1); g_csr[p] = s0.w;
        p = atomicAdd(&g_woff[d1.x], 1); g_csr[p] = s1.x;
        p = atomicAdd(&g_woff[d1.y], 1); g_csr[p] = s1.y;
        p = atomicAdd(&g_woff[d1.z], 1); g_csr[p] = s1.z;
        p = atomicAdd(&g_woff[d1.w], 1); g_csr[p] = s1.w;
    }
}

// ---- K4: layer-1 projections: xw0 = x@w1_0 + b1, xp1 = dinv*(x@w1_1) ----
__global__ void k_proj1(const float* __restrict__ x,
                        const float* __restrict__ w0,
                        const float* __restrict__ w1,
                        const float* __restrict__ b1) {
    __shared__ float sw0[N_FEAT * HIDDEN];
    __shared__ float sw1[N_FEAT * HIDDEN];
    __shared__ float sb[HIDDEN];
    for (int i = threadIdx.x; i < N_FEAT * HIDDEN; i += blockDim.x) {
        sw0[i] = w0[i];
        sw1[i] = w1[i];
    }
    if (threadIdx.x < HIDDEN) sb[threadIdx.x] = b1[threadIdx.x];
    __syncthreads();

    int n = blockIdx.x * blockDim.x + threadIdx.x;
    if (n >= N_NODES) return;

    float a0[HIDDEN];
    float a1[HIDDEN];
#pragma unroll
    for (int c = 0; c < HIDDEN; c++) { a0[c] = 0.0f; a1[c] = 0.0f; }

    const float2* xr = (const float2*)(x + (size_t)n * N_FEAT);  // 50 even
#pragma unroll 5
    for (int k2 = 0; k2 < N_FEAT / 2; k2++) {
        float2 xv = __ldg(&xr[k2]);
#pragma unroll
        for (int c = 0; c < HIDDEN; c++) {
            a0[c] = fmaf(xv.x, sw0[(2 * k2) * HIDDEN + c], a0[c]);
            a1[c] = fmaf(xv.x, sw1[(2 * k2) * HIDDEN + c], a1[c]);
            a0[c] = fmaf(xv.y, sw0[(2 * k2 + 1) * HIDDEN + c], a0[c]);
            a1[c] = fmaf(xv.y, sw1[(2 * k2 + 1) * HIDDEN + c], a1[c]);
        }
    }
    float dn = g_dinv[n];
    float4* o0 = (float4*)(g_xw0 + (size_t)n * HIDDEN);
    float4* o1 = (float4*)(g_xp1 + (size_t)n * HIDDEN);
#pragma unroll
    for (int q = 0; q < 4; q++) {
        float4 v0, v1;
        v0.x = a0[q * 4 + 0] + sb[q * 4 + 0];
        v0.y = a0[q * 4 + 1] + sb[q * 4 + 1];
        v0.z = a0[q * 4 + 2] + sb[q * 4 + 2];
        v0.w = a0[q * 4 + 3] + sb[q * 4 + 3];
        v1.x = dn * a1[q * 4 + 0];
        v1.y = dn * a1[q * 4 + 1];
        v1.z = dn * a1[q * 4 + 2];
        v1.w = dn * a1[q * 4 + 3];
        o0[q] = v0;
        o1[q] = v1;
    }
}

// ---- K5: fused layer-1 agg + relu + layer-2 proj. 4 lanes/node, float4. ----
__global__ void k_agg1p2(const float* __restrict__ w0,
                         const float* __restrict__ w1,
                         const float* __restrict__ b2) {
    __shared__ float4 sw0v[HIDDEN * 4];   // [k][q] -> cols q*4..q*4+3, pad 0
    __shared__ float4 sw1v[HIDDEN * 4];
    __shared__ float4 sbv[4];
    int t = threadIdx.x;
    {
        int k = t >> 4, c = t & 15;       // 256 threads cover 16x16
        ((float*)sw0v)[t] = (c < N_CLASSES) ? w0[k * N_CLASSES + c] : 0.0f;
        ((float*)sw1v)[t] = (c < N_CLASSES) ? w1[k * N_CLASSES + c] : 0.0f;
    }
    if (t < HIDDEN) ((float*)sbv)[t] = (t < N_CLASSES) ? b2[t] : 0.0f;
    __syncthreads();

    int gid  = blockIdx.x * blockDim.x + t;   // N_NODES*4 threads (guarded)
    int node = gid >> 2;
    int q    = gid & 3;
    if (node >= N_NODES) return;

    int b = g_rowptr[node];
    int e = g_rowptr[node + 1];
    const float4* xp = (const float4*)g_xp1;
    float4 acc = make_float4(0.f, 0.f, 0.f, 0.f);
    int j = b;
    for (; j + 4 <= e; j += 4) {
        int s0 = __ldg(&g_csr[j + 0]);
        int s1 = __ldg(&g_csr[j + 1]);
        int s2 = __ldg(&g_csr[j + 2]);
        int s3 = __ldg(&g_csr[j + 3]);
        float4 v0 = __ldg(&xp[s0 * 4 + q]);
        float4 v1 = __ldg(&xp[s1 * 4 + q]);
        float4 v2 = __ldg(&xp[s2 * 4 + q]);
        float4 v3 = __ldg(&xp[s3 * 4 + q]);
        acc.x += (v0.x + v1.x) + (v2.x + v3.x);
        acc.y += (v0.y + v1.y) + (v2.y + v3.y);
        acc.z += (v0.z + v1.z) + (v2.z + v3.z);
        acc.w += (v0.w + v1.w) + (v2.w + v3.w);
    }
    for (; j < e; j++) {
        int s = __ldg(&g_csr[j]);
        float4 v = __ldg(&xp[s * 4 + q]);
        acc.x += v.x; acc.y += v.y; acc.z += v.z; acc.w += v.w;
    }
    float dn = g_dinv[node];
    float4 sf = ((const float4*)g_xw0)[node * 4 + q];
    float4 h;
    h.x = fmaxf(sf.x + dn * acc.x, 0.0f);
    h.y = fmaxf(sf.y + dn * acc.y, 0.0f);
    h.z = fmaxf(sf.z + dn * acc.z, 0.0f);
    h.w = fmaxf(sf.w + dn * acc.w, 0.0f);

    // layer-2 projection via width-4 shuffle matmul
    float4 A0 = sbv[q];
    float4 A1 = make_float4(0.f, 0.f, 0.f, 0.f);
#pragma unroll
    for (int k = 0; k < HIDDEN; k++) {
        float comp = ((k & 3) == 0) ? h.x : ((k & 3) == 1) ? h.y
                   : ((k & 3) == 2) ? h.z : h.w;
        float hk = __shfl_sync(0xffffffffu, comp, k >> 2, 4);
        float4 w0v = sw0v[k * 4 + q];
        float4 w1v = sw1v[k * 4 + q];
        A0.x = fmaf(hk, w0v.x, A0.x); A0.y = fmaf(hk, w0v.y, A0.y);
        A0.z = fmaf(hk, w0v.z, A0.z); A0.w = fmaf(hk, w0v.w, A0.w);
        A1.x = fmaf(hk, w1v.x, A1.x); A1.y = fmaf(hk, w1v.y, A1.y);
        A1.z = fmaf(hk, w1v.z, A1.z); A1.w = fmaf(hk, w1v.w, A1.w);
    }
    ((float4*)g_hw)[node * 4 + q] = A0;
    float4 P;
    P.x = dn * A1.x; P.y = dn * A1.y; P.z = dn * A1.z; P.w = dn * A1.w;
    ((float4*)g_hp)[node * 4 + q] = P;
}

// ---- K6: layer-2 aggregation + log_softmax. 4 lanes/node, float4. ----
__global__ void k_agg2(float* __restrict__ out) {
    int gid  = blockIdx.x * blockDim.x + threadIdx.x;
    int node = gid >> 2;
    int q    = gid & 3;
    if (node >= N_NODES) return;

    int b = g_rowptr[node];
    int e = g_rowptr[node + 1];
    const float4* hp = (const float4*)g_hp;
    float4 acc = make_float4(0.f, 0.f, 0.f, 0.f);
    int j = b;
    for (; j + 4 <= e; j += 4) {
        int s0 = __ldg(&g_csr[j + 0]);
        int s1 = __ldg(&g_csr[j + 1]);
        int s2 = __ldg(&g_csr[j + 2]);
        int s3 = __ldg(&g_csr[j + 3]);
        float4 v0 = __ldg(&hp[s0 * 4 + q]);
        float4 v1 = __ldg(&hp[s1 * 4 + q]);
        float4 v2 = __ldg(&hp[s2 * 4 + q]);
        float4 v3 = __ldg(&hp[s3 * 4 + q]);
        acc.x += (v0.x + v1.x) + (v2.x + v3.x);
        acc.y += (v0.y + v1.y) + (v2.y + v3.y);
        acc.z += (v0.z + v1.z) + (v2.z + v3.z);
        acc.w += (v0.w + v1.w) + (v2.w + v3.w);
    }
    for (; j < e; j++) {
        int s = __ldg(&g_csr[j]);
        float4 v = __ldg(&hp[s * 4 + q]);
        acc.x += v.x; acc.y += v.y; acc.z += v.z; acc.w += v.w;
    }
    float dn = g_dinv[node];
    float4 sf = ((const float4*)g_hw)[node * 4 + q];
    float4 L;
    L.x = sf.x + dn * acc.x;
    L.y = sf.y + dn * acc.y;
    L.z = sf.z + dn * acc.z;
    L.w = sf.w + dn * acc.w;

    // log_softmax over c = q*4+i, valid c < 10
    int cb = q * 4;
    float m = -1e30f;
    if (cb + 0 < N_CLASSES) m = fmaxf(m, L.x);
    if (cb + 1 < N_CLASSES) m = fmaxf(m, L.y);
    if (cb + 2 < N_CLASSES) m = fmaxf(m, L.z);
    if (cb + 3 < N_CLASSES) m = fmaxf(m, L.w);
#pragma unroll
    for (int o = 1; o < 4; o <<= 1)
        m = fmaxf(m, __shfl_xor_sync(0xffffffffu, m, o, 4));
    float s = 0.0f;
    if (cb + 0 < N_CLASSES) s += expf(L.x - m);
    if (cb + 1 < N_CLASSES) s += expf(L.y - m);
    if (cb + 2 < N_CLASSES) s += expf(L.z - m);
    if (cb + 3 < N_CLASSES) s += expf(L.w - m);
#pragma unroll
    for (int o = 1; o < 4; o <<= 1)
        s += __shfl_xor_sync(0xffffffffu, s, o, 4);
    float lse = m + logf(s);

    float* op = out + (size_t)node * N_CLASSES;
    if (q == 0) {
        ((float2*)op)[0] = make_float2(L.x - lse, L.y - lse);
        ((float2*)op)[1] = make_float2(L.z - lse, L.w - lse);
    } else if (q == 1) {
        ((float2*)(op + 4))[0] = make_float2(L.x - lse, L.y - lse);
        ((float2*)(op + 4))[1] = make_float2(L.z - lse, L.w - lse);
    } else if (q == 2) {
        ((float2*)(op + 8))[0] = make_float2(L.x - lse, L.y - lse);
    }
}

extern "C" void kernel_launch(void* const* d_in, const int* in_sizes, int n_in,
                              void* d_out, int out_size) {
    const float* x    = (const float*)d_in[0];
    const int*   ei   = (const int*)d_in[1];     // int32: JAX x64 disabled
    const float* w1_0 = (const float*)d_in[2];
    const float* w1_1 = (const float*)d_in[3];
    const float* b1   = (const float*)d_in[4];
    const float* w2_0 = (const float*)d_in[5];
    const float* w2_1 = (const float*)d_in[6];
    const float* b2   = (const float*)d_in[7];
    float* out = (float*)d_out;

    const int E8 = N_EDGES / 8;                  // 200000
    const int GA = (N_NODES * 4 + 255) / 256;    // 1563
    k_count  <<<(E8 + 255) / 256, 256>>>(ei);
    k_red    <<<NB_SCAN, 256>>>();
    k_scanb  <<<1, 512>>>();
    k_scanc  <<<NB_SCAN, 256>>>();
    k_scatter<<<(E8 + 255) / 256, 256>>>(ei);
    k_proj1  <<<(N_NODES + 255) / 256, 256>>>(x, w1_0, w1_1, b1);
    k_agg1p2 <<<GA, 256>>>(w2_0, w2_1, b2);
    k_agg2   <<<GA, 256>>>(out);
}